// round 12
// baseline (speedup 1.0000x reference)
#include <cuda_runtime.h>
#include <cuda_bf16.h>
#include <cstdint>

#define BB 8
#define TT 2048
#define DD 1024
#define QD 128

// ---------------- global scratch ----------------
__device__ __nv_bfloat16 g_x_hi[(size_t)BB*TT*DD];
__device__ __nv_bfloat16 g_x_lo[(size_t)BB*TT*DD];
__device__ __nv_bfloat16 g_w_hi[3*QD*DD];
__device__ __nv_bfloat16 g_w_lo[3*QD*DD];
__device__ __nv_bfloat16 g_q_hi[BB*TT*QD];
__device__ __nv_bfloat16 g_q_lo[BB*TT*QD];
__device__ __nv_bfloat16 g_k_hi[BB*TT*QD];
__device__ __nv_bfloat16 g_k_lo[BB*TT*QD];
__device__ __nv_bfloat16 g_v_hi[BB*TT*QD];           // row-major [b][t][d]
__device__ __nv_bfloat16 g_v_lo[BB*TT*QD];
__device__ float g_mask[BB*TT];
__device__ int   g_mask_kind;

// ---------------- helpers ----------------
__device__ __forceinline__ uint32_t smem_u32(const void* p) {
    uint32_t a;
    asm("{ .reg .u64 t; cvta.to.shared.u64 t, %1; cvt.u32.u64 %0, t; }" : "=r"(a) : "l"(p));
    return a;
}
__device__ __forceinline__ uint32_t pk(__nv_bfloat16 a, __nv_bfloat16 b) {
    return (uint32_t)__bfloat16_as_ushort(a) | ((uint32_t)__bfloat16_as_ushort(b) << 16);
}
__device__ __forceinline__ void split2(float a, float b, uint32_t& h, uint32_t& l) {
    __nv_bfloat16 ha = __float2bfloat16_rn(a);
    __nv_bfloat16 hb = __float2bfloat16_rn(b);
    __nv_bfloat16 la = __float2bfloat16_rn(a - __bfloat162float(ha));
    __nv_bfloat16 lb = __float2bfloat16_rn(b - __bfloat162float(hb));
    h = pk(ha, hb); l = pk(la, lb);
}
__device__ __forceinline__ void ldm4(uint32_t r[4], uint32_t a) {
    asm volatile("ldmatrix.sync.aligned.m8n8.x4.shared.b16 {%0,%1,%2,%3}, [%4];"
        : "=r"(r[0]), "=r"(r[1]), "=r"(r[2]), "=r"(r[3]) : "r"(a));
}
__device__ __forceinline__ void ldm4t(uint32_t r[4], uint32_t a) {
    asm volatile("ldmatrix.sync.aligned.m8n8.x4.trans.shared.b16 {%0,%1,%2,%3}, [%4];"
        : "=r"(r[0]), "=r"(r[1]), "=r"(r[2]), "=r"(r[3]) : "r"(a));
}
__device__ __forceinline__ void mma_bf16(float* c, const uint32_t* a, const uint32_t* b) {
    asm volatile("mma.sync.aligned.m16n8k16.row.col.f32.bf16.bf16.f32 "
        "{%0,%1,%2,%3}, {%4,%5,%6,%7}, {%8,%9}, {%0,%1,%2,%3};"
        : "+f"(c[0]), "+f"(c[1]), "+f"(c[2]), "+f"(c[3])
        : "r"(a[0]), "r"(a[1]), "r"(a[2]), "r"(a[3]), "r"(b[0]), "r"(b[1]));
}
__device__ __forceinline__ void cp16(uint32_t dst, const void* src) {
    asm volatile("cp.async.cg.shared.global [%0], [%1], 16;"
        :: "r"(dst), "l"(__cvta_generic_to_global(src)) : "memory");
}
#define CP_COMMIT() asm volatile("cp.async.commit_group;" ::: "memory")
#define CP_WAIT(n)  asm volatile("cp.async.wait_group %0;" :: "n"(n) : "memory")

// ---------------- mask canonicalization (proven) ----------------
__global__ void mask_sniff(const uint8_t* __restrict__ m) {
    __shared__ unsigned r1[256], r3[256];
    unsigned o1 = 0, o3 = 0;
    const uint32_t* w = (const uint32_t*)m;
    for (int i = threadIdx.x; i < (BB*TT)/4; i += 256) {
        uint32_t v = w[i];
        o1 |= (v >> 8) & 0xFFu; o3 |= (v >> 24) & 0xFFu;
    }
    r1[threadIdx.x] = o1; r3[threadIdx.x] = o3;
    __syncthreads();
    for (int s = 128; s; s >>= 1) {
        if (threadIdx.x < s) { r1[threadIdx.x] |= r1[threadIdx.x+s]; r3[threadIdx.x] |= r3[threadIdx.x+s]; }
        __syncthreads();
    }
    if (threadIdx.x == 0) g_mask_kind = r1[0] ? 1 : (r3[0] ? 2 : 0);
}
__global__ void mask_expand(const void* __restrict__ m) {
    int s = blockIdx.x * 256 + threadIdx.x;
    if (s >= BB*TT) return;
    int kind = g_mask_kind;
    float v;
    if (kind == 1)      v = ((const uint8_t*)m)[s] ? 1.0f : 0.0f;
    else if (kind == 2) v = (((const float*)m)[s] != 0.0f) ? 1.0f : 0.0f;
    else                v = ((const int*)m)[s] ? 1.0f : 0.0f;
    g_mask[s] = v;
}

// ---------------- prep: split x and W into bf16 hi/lo ----------------
__global__ __launch_bounds__(256) void prep_kernel(
    const float* __restrict__ x,  const float* __restrict__ Wq,
    const float* __restrict__ Wk, const float* __restrict__ Wv)
{
    const int y = blockIdx.y;
    const size_t i = (size_t)blockIdx.x * 256 + threadIdx.x;
    const float* src; __nv_bfloat16 *dh, *dl; size_t n4;
    if (y == 0) { src = x; dh = g_x_hi; dl = g_x_lo; n4 = (size_t)BB*TT*DD/4; }
    else {
        src = (y == 1) ? Wq : ((y == 2) ? Wk : Wv);
        dh = g_w_hi + (size_t)(y-1)*QD*DD; dl = g_w_lo + (size_t)(y-1)*QD*DD;
        n4 = (size_t)QD*DD/4;
    }
    if (i >= n4) return;
    float4 v = ((const float4*)src)[i];
    uint32_t h01, l01, h23, l23;
    split2(v.x, v.y, h01, l01);
    split2(v.z, v.w, h23, l23);
    ((uint2*)dh)[i] = make_uint2(h01, h23);
    ((uint2*)dl)[i] = make_uint2(l01, l23);
}

// ---------------- projection GEMM (bf16x3, cp.async, 512 threads) ----------------
// grid (128 m-tiles, 3 ops), 512 thr = 16 warps (4x4), warp tile 32x32, BK=64.
#define PJ_AH 0
#define PJ_AL 16384
#define PJ_BH 32768
#define PJ_BL 49152
#define PJ_STAGE 65536
#define PJ_SMEM (2*PJ_STAGE + 1024)

__global__ __launch_bounds__(512, 1) void proj_kernel()
{
    extern __shared__ char smraw[];
    char* sp = (char*)(((uintptr_t)smraw + 1023) & ~(uintptr_t)1023);
    uint32_t sb = smem_u32(sp);
    const int tid = threadIdx.x, lane = tid & 31, w = tid >> 5;
    const int m0 = blockIdx.x * 128, z = blockIdx.y;
    const int wm = w & 3, wn = w >> 2;
    const int mrow0 = wm * 32, ncol0 = wn * 32;

    const __nv_bfloat16* xh = g_x_hi;
    const __nv_bfloat16* xl = g_x_lo;
    const __nv_bfloat16* wh = g_w_hi + (size_t)z*QD*DD;
    const __nv_bfloat16* wl = g_w_lo + (size_t)z*QD*DD;

    const int mat = lane >> 3;
    const uint32_t xorv = (uint32_t)(lane & 7) << 4;
    const int rA = (mat & 1) * 8 + (lane & 7);
    const int cA = (mat >> 1) * 16;
    const int rB = (mat >> 1) * 8 + (lane & 7);
    const int cB = (mat & 1) * 16;

    const int srow = tid >> 3, sci = tid & 7;     // staging: 64 rows per pass
    float C[2][4][4] = {};

    #define PJ_STAGE_CHUNK(c) do {                                              \
        const int _k0 = (c) * 64;                                               \
        uint32_t _bb = sb + (uint32_t)((c) & 1) * PJ_STAGE;                     \
        _Pragma("unroll")                                                       \
        for (int _r = 0; _r < 2; _r++) {                                        \
            int _row = srow + _r * 64;                                          \
            uint32_t _doff = (uint32_t)_row * 128 +                             \
                (((uint32_t)sci * 16) ^ ((uint32_t)(_row & 7) << 4));           \
            const size_t _go = (size_t)(m0 + _row) * DD + _k0 + sci * 8;        \
            const size_t _gw = (size_t)_row * DD + _k0 + sci * 8;               \
            cp16(_bb + PJ_AH + _doff, xh + _go);                                \
            cp16(_bb + PJ_AL + _doff, xl + _go);                                \
            cp16(_bb + PJ_BH + _doff, wh + _gw);                                \
            cp16(_bb + PJ_BL + _doff, wl + _gw);                                \
        } } while (0)

    PJ_STAGE_CHUNK(0); CP_COMMIT();

    for (int c = 0; c < 16; c++) {
        if (c + 1 < 16) { PJ_STAGE_CHUNK(c + 1); CP_COMMIT(); CP_WAIT(1); }
        else            { CP_WAIT(0); }
        __syncthreads();
        const uint32_t bb = sb + (uint32_t)(c & 1) * PJ_STAGE;

        #pragma unroll
        for (int ks = 0; ks < 4; ks++) {
            const int k0 = ks * 16;
            uint32_t ah[2][4], al[2][4];
            #pragma unroll
            for (int mt = 0; mt < 2; mt++) {
                uint32_t aoff = (uint32_t)(mrow0 + mt*16 + rA) * 128 + (((uint32_t)(k0*2 + cA)) ^ xorv);
                ldm4(ah[mt], bb + PJ_AH + aoff);
                ldm4(al[mt], bb + PJ_AL + aoff);
            }
            uint32_t bh[2][4], bl[2][4];
            #pragma unroll
            for (int nt2 = 0; nt2 < 2; nt2++) {
                const int n0 = ncol0 + nt2 * 16;
                uint32_t boff = (uint32_t)(n0 + rB) * 128 + (((uint32_t)(k0*2 + cB)) ^ xorv);
                ldm4(bh[nt2], bb + PJ_BH + boff);
                ldm4(bl[nt2], bb + PJ_BL + boff);
            }
            #pragma unroll
            for (int nt2 = 0; nt2 < 2; nt2++)
                #pragma unroll
                for (int mt = 0; mt < 2; mt++) {
                    mma_bf16(C[mt][nt2*2],   ah[mt], bh[nt2]);
                    mma_bf16(C[mt][nt2*2+1], ah[mt], bh[nt2] + 2);
                }
            #pragma unroll
            for (int nt2 = 0; nt2 < 2; nt2++)
                #pragma unroll
                for (int mt = 0; mt < 2; mt++) {
                    mma_bf16(C[mt][nt2*2],   ah[mt], bl[nt2]);
                    mma_bf16(C[mt][nt2*2+1], ah[mt], bl[nt2] + 2);
                }
            #pragma unroll
            for (int nt2 = 0; nt2 < 2; nt2++)
                #pragma unroll
                for (int mt = 0; mt < 2; mt++) {
                    mma_bf16(C[mt][nt2*2],   al[mt], bh[nt2]);
                    mma_bf16(C[mt][nt2*2+1], al[mt], bh[nt2] + 2);
                }
        }
        __syncthreads();
    }

    __nv_bfloat16 *dh, *dl;
    if (z == 0)      { dh = g_q_hi; dl = g_q_lo; }
    else if (z == 1) { dh = g_k_hi; dl = g_k_lo; }
    else             { dh = g_v_hi; dl = g_v_lo; }
    const int r = lane >> 2, c2 = 2 * (lane & 3);
    #pragma unroll
    for (int mt = 0; mt < 2; mt++) {
        #pragma unroll
        for (int nt = 0; nt < 4; nt++) {
            int cc = ncol0 + nt * 8 + c2;
            size_t mg0 = (size_t)(m0 + mrow0 + mt*16 + r);
            uint32_t h, l;
            split2(C[mt][nt][0], C[mt][nt][1], h, l);
            *(uint32_t*)(dh + mg0*QD + cc) = h;
            *(uint32_t*)(dl + mg0*QD + cc) = l;
            split2(C[mt][nt][2], C[mt][nt][3], h, l);
            *(uint32_t*)(dh + (mg0+8)*QD + cc) = h;
            *(uint32_t*)(dl + (mg0+8)*QD + cc) = l;
        }
    }
}

// ---------------- flash attention v2: 64 q-rows/CTA, warp-pair key split ----------------
// grid (32 q-tiles, 8 batches), 256 thr, 2 CTAs/SM. Warp w: q-rows (w&3)*16..+16,
// key half h=w>>2 (32 of each 64-key tile). Pair (w, w+4) syncs m/s each iter
// via smem; O partials merged once at the end.
#define A2_QH 0
#define A2_QL 16384
#define A2_KH 32768
#define A2_KL 49152
#define A2_VH 65536
#define A2_VL 81920
#define A2_MK 98304
#define A2_RM 98560
#define A2_RS 99072
#define A2_OEX 32768          // reuse K region for final O exchange (32KB)
#define A2_SMEM (99584 + 1024)

__global__ __launch_bounds__(256, 2) void attn_kernel(float* __restrict__ out)
{
    extern __shared__ char smraw[];
    char* sp = (char*)(((uintptr_t)smraw + 1023) & ~(uintptr_t)1023);
    uint32_t sb = smem_u32(sp);
    float* mkS  = (float*)(sp + A2_MK);
    float* redM = (float*)(sp + A2_RM);
    float* redS = (float*)(sp + A2_RS);
    const int tid = threadIdx.x, lane = tid & 31, w = tid >> 5;
    const int b = blockIdx.y, t0 = blockIdx.x * 64;
    const int rb = w & 3, h = w >> 2;
    const int m0w = rb * 16;

    const int mat = lane >> 3;
    const uint32_t xorv = (uint32_t)(lane & 7) << 4;
    const int rA = (mat & 1) * 8 + (lane & 7);
    const int cA = (mat >> 1) * 16;
    const int rB = (mat >> 1) * 8 + (lane & 7);
    const int cB = (mat & 1) * 16;

    const int srow = tid >> 4, sci = tid & 15;   // staging: 16 rows per pass

    #define A2_ISSUE_K(it) do {                                                 \
        const int _s0 = (it) * 64;                                              \
        _Pragma("unroll")                                                       \
        for (int _r = 0; _r < 4; _r++) {                                        \
            int _row = srow + _r * 16;                                          \
            uint32_t _doff = (uint32_t)_row * 256 +                             \
                (((uint32_t)sci * 16) ^ ((uint32_t)(_row & 7) << 4));           \
            const size_t _g = (size_t)(b*TT + _s0 + _row) * QD + sci * 8;       \
            cp16(sb + A2_KH + _doff, g_k_hi + _g);                              \
            cp16(sb + A2_KL + _doff, g_k_lo + _g);                              \
        }                                                                       \
        if (tid < 16) cp16(sb + A2_MK + tid*16, g_mask + b*TT + _s0 + tid*4);   \
    } while (0)

    #define A2_ISSUE_V(it) do {                                                 \
        const int _s0 = (it) * 64;                                              \
        _Pragma("unroll")                                                       \
        for (int _r = 0; _r < 4; _r++) {                                        \
            int _row = srow + _r * 16;                                          \
            uint32_t _doff = (uint32_t)_row * 256 +                             \
                (((uint32_t)sci * 16) ^ ((uint32_t)(_row & 7) << 4));           \
            const size_t _g = (size_t)(b*TT + _s0 + _row) * QD + sci * 8;       \
            cp16(sb + A2_VH + _doff, g_v_hi + _g);                              \
            cp16(sb + A2_VL + _doff, g_v_lo + _g);                              \
        } } while (0)

    A2_ISSUE_K(0); CP_COMMIT();
    A2_ISSUE_V(0); CP_COMMIT();

    // stage Q tile 64x128 hi/lo
    {
        const uint4* qh = (const uint4*)(g_q_hi + (size_t)(b*TT + t0) * QD);
        const uint4* ql = (const uint4*)(g_q_lo + (size_t)(b*TT + t0) * QD);
        #pragma unroll
        for (int r = 0; r < 4; r++) {
            int idx = tid + r * 256;
            int row = idx >> 4;
            uint32_t cb = (uint32_t)(idx & 15) * 16;
            uint32_t doff = (uint32_t)row * 256 + (cb ^ ((uint32_t)(row & 7) << 4));
            *(uint4*)(sp + A2_QH + doff) = qh[idx];
            *(uint4*)(sp + A2_QL + doff) = ql[idx];
        }
    }

    float O[16][4] = {};
    float m0r = -1.0e30f, m1r = -1.0e30f, s0r = 0.0f, s1r = 0.0f;
    const int c2 = 2 * (lane & 3);
    const int r0c = m0w + (lane >> 2), r1c = r0c + 8;   // CTA-local rows

    for (int it = 0; it < 32; it++) {
        CP_WAIT(1);                  // K(it) arrived
        __syncthreads();             // B1

        // S = Q(16x128) . K_half^T(32 keys)
        float S[4][4] = {};
        #pragma unroll
        for (int ks = 0; ks < 8; ks++) {
            const int k0 = ks * 16;
            uint32_t aqh[4], aql[4];
            uint32_t aoff = (uint32_t)(m0w + rA) * 256 + (((uint32_t)(k0*2 + cA)) ^ xorv);
            ldm4(aqh, sb + A2_QH + aoff);
            ldm4(aql, sb + A2_QL + aoff);
            uint32_t bh[2][4], bl[2][4];
            #pragma unroll
            for (int nt2 = 0; nt2 < 2; nt2++) {
                const int n0 = h*32 + nt2 * 16;
                uint32_t boff = (uint32_t)(n0 + rB) * 256 + (((uint32_t)(k0*2 + cB)) ^ xorv);
                ldm4(bh[nt2], sb + A2_KH + boff);
                ldm4(bl[nt2], sb + A2_KL + boff);
            }
            #pragma unroll
            for (int nt2 = 0; nt2 < 2; nt2++) {
                mma_bf16(S[nt2*2],   aqh, bh[nt2]);
                mma_bf16(S[nt2*2+1], aqh, bh[nt2] + 2);
            }
            #pragma unroll
            for (int nt2 = 0; nt2 < 2; nt2++) {
                mma_bf16(S[nt2*2],   aqh, bl[nt2]);
                mma_bf16(S[nt2*2+1], aqh, bl[nt2] + 2);
            }
            #pragma unroll
            for (int nt2 = 0; nt2 < 2; nt2++) {
                mma_bf16(S[nt2*2],   aql, bh[nt2]);
                mma_bf16(S[nt2*2+1], aql, bh[nt2] + 2);
            }
        }

        // mask + own-half row max (over 32 keys)
        float mx0 = -3.0e38f, mx1 = -3.0e38f;
        #pragma unroll
        for (int nt = 0; nt < 4; nt++) {
            float k0m = mkS[h*32 + nt*8 + c2], k1m = mkS[h*32 + nt*8 + c2 + 1];
            S[nt][0] = (k0m != 0.0f) ? S[nt][0] : -3.0e38f;
            S[nt][1] = (k1m != 0.0f) ? S[nt][1] : -3.0e38f;
            S[nt][2] = (k0m != 0.0f) ? S[nt][2] : -3.0e38f;
            S[nt][3] = (k1m != 0.0f) ? S[nt][3] : -3.0e38f;
            mx0 = fmaxf(mx0, fmaxf(S[nt][0], S[nt][1]));
            mx1 = fmaxf(mx1, fmaxf(S[nt][2], S[nt][3]));
        }
        mx0 = fmaxf(mx0, __shfl_xor_sync(0xffffffffu, mx0, 1));
        mx0 = fmaxf(mx0, __shfl_xor_sync(0xffffffffu, mx0, 2));
        mx1 = fmaxf(mx1, __shfl_xor_sync(0xffffffffu, mx1, 1));
        mx1 = fmaxf(mx1, __shfl_xor_sync(0xffffffffu, mx1, 2));
        if ((lane & 3) == 0) { redM[h*64 + r0c] = mx0; redM[h*64 + r1c] = mx1; }
        __syncthreads();             // B2: pair maxes visible; all warps done reading K
        float om0 = redM[(1-h)*64 + r0c], om1 = redM[(1-h)*64 + r1c];
        float mn0 = fmaxf(m0r, fmaxf(mx0, om0));
        float mn1 = fmaxf(m1r, fmaxf(mx1, om1));
        float sc0 = __expf(m0r - mn0), sc1 = __expf(m1r - mn1);
        float sum0 = 0.0f, sum1 = 0.0f;
        #pragma unroll
        for (int nt = 0; nt < 4; nt++) {
            S[nt][0] = __expf(S[nt][0] - mn0);
            S[nt][1] = __expf(S[nt][1] - mn0);
            S[nt][2] = __expf(S[nt][2] - mn1);
            S[nt][3] = __expf(S[nt][3] - mn1);
            sum0 += S[nt][0] + S[nt][1];
            sum1 += S[nt][2] + S[nt][3];
        }
        sum0 += __shfl_xor_sync(0xffffffffu, sum0, 1);
        sum0 += __shfl_xor_sync(0xffffffffu, sum0, 2);
        sum1 += __shfl_xor_sync(0xffffffffu, sum1, 1);
        sum1 += __shfl_xor_sync(0xffffffffu, sum1, 2);
        if ((lane & 3) == 0) { redS[h*64 + r0c] = sum0; redS[h*64 + r1c] = sum1; }
        m0r = mn0;  m1r = mn1;

        if (it + 1 < 32) { A2_ISSUE_K(it + 1); CP_COMMIT(); CP_WAIT(1); }  // V(it) done
        else             { CP_WAIT(0); }
        __syncthreads();             // B3: V visible, pair sums visible

        s0r = s0r * sc0 + sum0 + redS[(1-h)*64 + r0c];
        s1r = s1r * sc1 + sum1 + redS[(1-h)*64 + r1c];
        #pragma unroll
        for (int nt = 0; nt < 16; nt++) {
            O[nt][0] *= sc0; O[nt][1] *= sc0;
            O[nt][2] *= sc1; O[nt][3] *= sc1;
        }

        // O += P(16x32) . V_half(32x128)
        #pragma unroll
        for (int ks = 0; ks < 2; ks++) {
            uint32_t ah[4], al[4];
            split2(S[2*ks][0],   S[2*ks][1],   ah[0], al[0]);
            split2(S[2*ks][2],   S[2*ks][3],   ah[1], al[1]);
            split2(S[2*ks+1][0], S[2*ks+1][1], ah[2], al[2]);
            split2(S[2*ks+1][2], S[2*ks+1][3], ah[3], al[3]);
            const int sv0 = h*32 + ks * 16;
            #pragma unroll
            for (int g = 0; g < 4; g++) {
                uint32_t bvh[2][4], bvl[2][4];
                #pragma unroll
                for (int j = 0; j < 2; j++) {
                    const int d0 = (g*2 + j) * 16;
                    uint32_t voff = (uint32_t)(sv0 + rA) * 256 + (((uint32_t)(d0*2 + cA)) ^ xorv);
                    ldm4t(bvh[j], sb + A2_VH + voff);
                    ldm4t(bvl[j], sb + A2_VL + voff);
                }
                #pragma unroll
                for (int j = 0; j < 2; j++) {
                    mma_bf16(O[(g*2+j)*2],   ah, bvh[j]);
                    mma_bf16(O[(g*2+j)*2+1], ah, bvh[j] + 2);
                }
                #pragma unroll
                for (int j = 0; j < 2; j++) {
                    mma_bf16(O[(g*2+j)*2],   ah, bvl[j]);
                    mma_bf16(O[(g*2+j)*2+1], ah, bvl[j] + 2);
                }
                #pragma unroll
                for (int j = 0; j < 2; j++) {
                    mma_bf16(O[(g*2+j)*2],   al, bvh[j]);
                    mma_bf16(O[(g*2+j)*2+1], al, bvh[j] + 2);
                }
            }
        }
        __syncthreads();             // B4: V consumed
        if (it + 1 < 32) { A2_ISSUE_V(it + 1); CP_COMMIT(); }
    }

    // merge pair halves: h==1 writes O partial, h==0 adds + stores
    float* oex = (float*)(sp + A2_OEX);
    if (h == 1) {
        #pragma unroll
        for (int nt = 0; nt < 16; nt++) {
            int col = nt * 8 + c2;
            *(float2*)(oex + r0c*128 + col) = make_float2(O[nt][0], O[nt][1]);
            *(float2*)(oex + r1c*128 + col) = make_float2(O[nt][2], O[nt][3]);
        }
    }
    __syncthreads();
    if (h == 0) {
        const float inv0 = (s0r > 0.0f) ? 1.0f / s0r : 0.0f;
        const float inv1 = (s1r > 0.0f) ? 1.0f / s1r : 0.0f;
        const size_t row0 = (size_t)b*TT + t0 + r0c;
        #pragma unroll
        for (int nt = 0; nt < 16; nt++) {
            int col = nt * 8 + c2;
            float2 p0 = *(float2*)(oex + r0c*128 + col);
            float2 p1 = *(float2*)(oex + r1c*128 + col);
            *(float2*)(out + row0*QD + col) =
                make_float2((O[nt][0] + p0.x)*inv0, (O[nt][1] + p0.y)*inv0);
            *(float2*)(out + (row0+8)*QD + col) =
                make_float2((O[nt][2] + p1.x)*inv1, (O[nt][3] + p1.y)*inv1);
        }
    }
}

// ---------------- launch ----------------
extern "C" void kernel_launch(void* const* d_in, const int* in_sizes, int n_in,
                              void* d_out, int out_size)
{
    const float* x  = (const float*)d_in[0];
    const void*  mk = d_in[1];
    const float* Wq = (const float*)d_in[2];
    const float* Wk = (const float*)d_in[3];
    const float* Wv = (const float*)d_in[4];
    float* out = (float*)d_out;
    (void)in_sizes; (void)n_in; (void)out_size;

    mask_sniff<<<1, 256>>>((const uint8_t*)mk);
    mask_expand<<<(BB*TT + 255)/256, 256>>>(mk);

    dim3 gp((BB*TT*DD/4 + 255)/256, 4);
    prep_kernel<<<gp, 256>>>(x, Wq, Wk, Wv);

    cudaFuncSetAttribute(proj_kernel, cudaFuncAttributeMaxDynamicSharedMemorySize, PJ_SMEM);
    cudaFuncSetAttribute(attn_kernel, cudaFuncAttributeMaxDynamicSharedMemorySize, A2_SMEM);

    dim3 g1(128, 3);
    proj_kernel<<<g1, 512, PJ_SMEM>>>();
    dim3 g2(TT/64, BB);
    attn_kernel<<<g2, 256, A2_SMEM>>>(out);
}